// round 5
// baseline (speedup 1.0000x reference)
#include <cuda_runtime.h>
#include <cuda_bf16.h>
#include <cstdint>

#define B_    32
#define CIN   256
#define COUT  256
#define Hs    56
#define Ws    56
#define HW    3136
#define Mtot  100352
#define Kdim  2304
#define KZERO 128
#define NCH   108          /* K'' / 64 = 6912/64 */
#define CHPP  36           /* chunks per split-pass */
#define BTILE 32768        /* bytes per pre-swizzled B chunk tile */

// ---------------- device scratch (static globals; no allocation) -----------
__device__ float d_s[B_*CIN];
__device__ float d_t[B_*COUT];
__device__ __nv_bfloat16 d_xhi[(size_t)B_*CIN*HW];
__device__ __nv_bfloat16 d_xlo[(size_t)B_*CIN*HW];
__device__ __align__(16) __nv_bfloat16 d_bimg[(size_t)NCH*256*64]; // pre-swizzled B tiles

// ---------------------------------------------------------------------------
// P0: split x into bf16 hi/lo + abs-mean
// ---------------------------------------------------------------------------
__global__ void prep_x_kernel(const float* __restrict__ x) {
    int bc = blockIdx.x;
    size_t base = (size_t)bc * HW;
    float sum = 0.f;
    for (int j = threadIdx.x; j < HW; j += 256) {
        float v = x[base + j];
        __nv_bfloat16 h = __float2bfloat16(v);
        d_xhi[base + j] = h;
        d_xlo[base + j] = __float2bfloat16(v - __bfloat162float(h));
        sum += fabsf(v);
    }
    __shared__ float red[256];
    red[threadIdx.x] = sum;
    __syncthreads();
    for (int s = 128; s > 0; s >>= 1) {
        if (threadIdx.x < s) red[threadIdx.x] += red[threadIdx.x + s];
        __syncthreads();
    }
    if (threadIdx.x == 0) d_s[bc] = red[0] * (1.0f / HW);
}

// ---------------------------------------------------------------------------
// P1: pre-swizzled B tile images (row n: 128B = 64 bf16 along k, SW128)
// ---------------------------------------------------------------------------
__global__ void prep_w_kernel(const float* __restrict__ cw) {
    int c = blockIdx.x;
    int n = threadIdx.x;
    int p = (c >= 2*CHPP) ? 2 : (c >= CHPP ? 1 : 0);
    int kbase = c*64 - p*Kdim;
    char* dst = (char*)d_bimg + (size_t)c * BTILE;
    const float* wr = cw + (size_t)n * Kdim + kbase;
    for (int kk = 0; kk < 64; kk++) {
        float v = wr[kk];
        __nv_bfloat16 h = __float2bfloat16(v);
        __nv_bfloat16 val = (p == 1) ? __float2bfloat16(v - __bfloat162float(h)) : h;
        uint32_t off = (uint32_t)(n*128 + kk*2);
        off ^= (off >> 3) & 0x70;
        *(__nv_bfloat16*)(dst + off) = val;
    }
}

// ---------------------------------------------------------------------------
// P2: gate
// ---------------------------------------------------------------------------
__global__ void gate_kernel(const float* __restrict__ gw,
                            const float* __restrict__ gb) {
    int b = blockIdx.x;
    int c = threadIdx.x;
    __shared__ float s_sh[CIN];
    __shared__ float g_sh[COUT];
    __shared__ float red[256];

    s_sh[c] = d_s[b*CIN + c];
    __syncthreads();

    const float* wrow = gw + (size_t)c * CIN;
    float acc = gb[c];
    #pragma unroll 8
    for (int j = 0; j < CIN; j++) acc = fmaf(s_sh[j], wrow[j], acc);
    float g = fmaxf(acc, 0.f);
    g_sh[c] = g;
    __syncthreads();

    int rank = 0;
    for (int j = 0; j < COUT; j++) {
        float gj = g_sh[j];
        rank += (gj < g) || (gj == g && j < c);
    }
    float t = (rank < KZERO) ? 0.f : g;

    red[c] = t;
    __syncthreads();
    for (int s = 128; s > 0; s >>= 1) {
        if (c < s) red[c] += red[c + s];
        __syncthreads();
    }
    d_t[b*COUT + c] = t * ((float)COUT / red[0]);
}

// ---------------------------------------------------------------------------
// Main: mma.sync bf16 implicit GEMM.
// CTA: 128 m x 256 n, 8 warps (256 thr), warp tile 64x64, K-chunk 64,
// double-buffered; B staged via cp.async, A via reg-prefetch gather.
// ---------------------------------------------------------------------------
#define SM_A    0
#define SM_B    32768
#define SM_KOFF 98304
#define SM_INV  107520
#define SM_ADD  108544
#define SMEM_SZ 109568

__device__ __forceinline__ uint32_t smem_u32(const void* p) {
    uint32_t a;
    asm("{ .reg .u64 t; cvta.to.shared.u64 t, %1; cvt.u32.u64 %0, t; }" : "=r"(a) : "l"(p));
    return a;
}
__device__ __forceinline__ void ldmx4(uint32_t* r, uint32_t addr) {
    asm volatile("ldmatrix.sync.aligned.m8n8.x4.shared.b16 {%0,%1,%2,%3}, [%4];"
        : "=r"(r[0]), "=r"(r[1]), "=r"(r[2]), "=r"(r[3]) : "r"(addr));
}
__device__ __forceinline__ void mma16816(float* c, const uint32_t* a, const uint32_t* b) {
    asm volatile(
        "mma.sync.aligned.m16n8k16.row.col.f32.bf16.bf16.f32 "
        "{%0,%1,%2,%3}, {%4,%5,%6,%7}, {%8,%9}, {%0,%1,%2,%3};"
        : "+f"(c[0]), "+f"(c[1]), "+f"(c[2]), "+f"(c[3])
        : "r"(a[0]), "r"(a[1]), "r"(a[2]), "r"(a[3]), "r"(b[0]), "r"(b[1]));
}
__device__ __forceinline__ uint32_t sw128(uint32_t off) {
    return off ^ ((off >> 3) & 0x70);
}
__device__ __forceinline__ void cp16(uint32_t saddr, const void* g) {
    asm volatile("cp.async.cg.shared.global [%0], [%1], 16;" :: "r"(saddr), "l"(g) : "memory");
}
#define CP_COMMIT() asm volatile("cp.async.commit_group;" ::: "memory")
#define CP_WAIT0()  asm volatile("cp.async.wait_group 0;" ::: "memory")

__global__ void __launch_bounds__(256, 1)
conv_mma_kernel(const float* __restrict__ gamma, const float* __restrict__ beta,
                const float* __restrict__ mean,  const float* __restrict__ var,
                float* __restrict__ out)
{
    extern __shared__ __align__(1024) char smem[];
    uint32_t* koff_s = (uint32_t*)(smem + SM_KOFF);
    float* inv_s = (float*)(smem + SM_INV);
    float* add_s = (float*)(smem + SM_ADD);
    const uint32_t su = smem_u32(smem);

    const int t = threadIdx.x;
    const int lane = t & 31;
    const int wrp = t >> 5;            // 0..7
    const int wm = (wrp & 1) * 64;     // warp m offset
    const int wn = (wrp >> 1) * 64;    // warp n offset

    // koff table: k -> (rs<<20) | (offset+64)
    for (int k = t; k < Kdim; k += 256) {
        int ci = k / 9, rs = k - ci*9;
        int dh = rs / 3, dw = rs - dh*3;
        int off = ci*HW + (dh-1)*Ws + (dw-1);
        koff_s[k] = ((uint32_t)rs << 20) | (uint32_t)(off + 64);
    }
    {
        float iv = gamma[t] * rsqrtf(var[t] + 1e-5f);
        inv_s[t] = iv;
        add_s[t] = beta[t] - mean[t]*iv;
    }
    __syncthreads();   // koff_s table must be complete before prologue reads

    // ---- A loader geometry: 2 threads per m-row, 8 k-groups each ----
    const int mtile = blockIdx.x * 128;
    const int r = t & 127;
    const int kgb = (t >> 7) * 8;      // 0 or 8
    const int m = mtile + r;
    const int bb = m / HW;
    const int rem = m - bb*HW;
    const int hh = rem / Ws;
    const int ww = rem - hh*Ws;
    const int boff = bb*(CIN*HW) + hh*Ws + ww;
    int msk = 0;
    #pragma unroll
    for (int rs = 0; rs < 9; rs++) {
        int dh = rs/3, dw = rs - dh*3;
        int hy = hh + dh - 1, wx = ww + dw - 1;
        if ((unsigned)hy < Hs && (unsigned)wx < Ws) msk |= (1 << rs);
    }
    uint32_t stA[8];
    #pragma unroll
    for (int q = 0; q < 8; q++)
        stA[q] = sw128((uint32_t)(r*128 + (kgb + q)*8));

    // ldmatrix lane geometry
    const int a_row = (lane & 15);
    const int a_kb  = (lane & 16) ? 16 : 0;
    const int b_row = ((lane & 16) ? 8 : 0) + (lane & 7);
    const int b_kb  = (lane & 8) ? 16 : 0;

    const unsigned short* xhi = (const unsigned short*)d_xhi;
    const unsigned short* xlo = (const unsigned short*)d_xlo;
    const char* bsrc = (const char*)d_bimg;

    float acc[4][8][4];
    #pragma unroll
    for (int i = 0; i < 4; i++)
        #pragma unroll
        for (int j = 0; j < 8; j++)
            #pragma unroll
            for (int q = 0; q < 4; q++) acc[i][j][q] = 0.f;

    // ---- prologue: chunk 0 into buf 0 ----
    {
        #pragma unroll
        for (int q = 0; q < 8; q++)
            cp16(su + SM_B + (uint32_t)(q*256 + t)*16, bsrc + (q*256 + t)*16);
        CP_COMMIT();
        char* abase = smem + SM_A;
        #pragma unroll
        for (int q = 0; q < 8; q++) {
            uint4 e = *(const uint4*)(koff_s + (kgb + q)*4);
            uint32_t v0 = ((msk >> (e.x >> 20)) & 1) ? (uint32_t)xhi[boff + (int)(e.x & 0xFFFFFu) - 64] : 0u;
            uint32_t v1 = ((msk >> (e.y >> 20)) & 1) ? (uint32_t)xhi[boff + (int)(e.y & 0xFFFFFu) - 64] : 0u;
            uint32_t v2 = ((msk >> (e.z >> 20)) & 1) ? (uint32_t)xhi[boff + (int)(e.z & 0xFFFFFu) - 64] : 0u;
            uint32_t v3 = ((msk >> (e.w >> 20)) & 1) ? (uint32_t)xhi[boff + (int)(e.w & 0xFFFFFu) - 64] : 0u;
            *(uint2*)(abase + stA[q]) = make_uint2(v0 | (v1 << 16), v2 | (v3 << 16));
        }
        CP_WAIT0();
    }
    __syncthreads();

    for (int c = 0; c < NCH; c++) {
        const int buf = c & 1;
        const bool more = (c + 1 < NCH);

        // ---- issue next-chunk loads ----
        uint2 sA[8];
        if (more) {
            const int cn = c + 1;
            const char* src = bsrc + (size_t)cn * BTILE;
            const uint32_t bdst = su + SM_B + (uint32_t)(buf^1)*BTILE;
            #pragma unroll
            for (int q = 0; q < 8; q++)
                cp16(bdst + (uint32_t)(q*256 + t)*16, src + (q*256 + t)*16);
            CP_COMMIT();
            const int p = (cn >= 2*CHPP) ? 2 : (cn >= CHPP ? 1 : 0);
            const unsigned short* sx = (p == 2) ? xlo : xhi;
            const int k0 = cn*64 - p*Kdim;
            #pragma unroll
            for (int q = 0; q < 8; q++) {
                uint4 e = *(const uint4*)(koff_s + k0 + (kgb + q)*4);
                uint32_t v0 = ((msk >> (e.x >> 20)) & 1) ? (uint32_t)sx[boff + (int)(e.x & 0xFFFFFu) - 64] : 0u;
                uint32_t v1 = ((msk >> (e.y >> 20)) & 1) ? (uint32_t)sx[boff + (int)(e.y & 0xFFFFFu) - 64] : 0u;
                uint32_t v2 = ((msk >> (e.z >> 20)) & 1) ? (uint32_t)sx[boff + (int)(e.z & 0xFFFFFu) - 64] : 0u;
                uint32_t v3 = ((msk >> (e.w >> 20)) & 1) ? (uint32_t)sx[boff + (int)(e.w & 0xFFFFFu) - 64] : 0u;
                sA[q] = make_uint2(v0 | (v1 << 16), v2 | (v3 << 16));
            }
        }

        // ---- compute 4 k16 steps from buf ----
        const uint32_t Ab = su + SM_A + buf*16384;
        const uint32_t Bb = su + SM_B + buf*BTILE;
        #pragma unroll
        for (int ks = 0; ks < 4; ks++) {
            uint32_t af[4][4];
            #pragma unroll
            for (int am = 0; am < 4; am++) {
                uint32_t off = (uint32_t)((wm + am*16 + a_row)*128 + ks*32 + a_kb);
                ldmx4(af[am], Ab + sw128(off));
            }
            uint32_t bf[8][2];
            #pragma unroll
            for (int bp = 0; bp < 4; bp++) {
                uint32_t rr[4];
                uint32_t off = (uint32_t)((wn + bp*16 + b_row)*128 + ks*32 + b_kb);
                ldmx4(rr, Bb + sw128(off));
                bf[2*bp][0] = rr[0]; bf[2*bp][1] = rr[1];
                bf[2*bp+1][0] = rr[2]; bf[2*bp+1][1] = rr[3];
            }
            #pragma unroll
            for (int am = 0; am < 4; am++)
                #pragma unroll
                for (int bn = 0; bn < 8; bn++)
                    mma16816(acc[am][bn], af[am], bf[bn]);
        }

        // ---- drain staged A, wait B cp.async, flip ----
        if (more) {
            char* abase = smem + SM_A + (buf^1)*16384;
            #pragma unroll
            for (int q = 0; q < 8; q++)
                *(uint2*)(abase + stA[q]) = sA[q];
            CP_WAIT0();
        }
        __syncthreads();
    }

    // ---- epilogue: BN + ReLU + gate, write NCHW ----
    #pragma unroll
    for (int am = 0; am < 4; am++) {
        int mr0 = mtile + wm + am*16 + (lane >> 2);
        #pragma unroll
        for (int half = 0; half < 2; half++) {
            int mr = mr0 + half*8;
            int b = mr / HW;
            int rm = mr - b*HW;
            float* op = out + (size_t)b*(COUT*HW) + rm;
            const float* tp = d_t + b*COUT;
            #pragma unroll
            for (int bn = 0; bn < 8; bn++) {
                int n = wn + bn*8 + 2*(lane & 3);
                float v0 = fmaf(acc[am][bn][half*2+0], inv_s[n],   add_s[n]);
                float v1 = fmaf(acc[am][bn][half*2+1], inv_s[n+1], add_s[n+1]);
                v0 = fmaxf(v0, 0.f) * __ldg(tp + n);
                v1 = fmaxf(v1, 0.f) * __ldg(tp + n + 1);
                op[(size_t)n * HW] = v0;
                op[(size_t)(n+1) * HW] = v1;
            }
        }
    }
}

// ---------------------------------------------------------------------------
extern "C" void kernel_launch(void* const* d_in, const int* in_sizes, int n_in,
                              void* d_out, int out_size) {
    const float* x     = (const float*)d_in[0];
    const float* cw    = (const float*)d_in[1];
    const float* gw    = (const float*)d_in[2];
    const float* gb    = (const float*)d_in[3];
    const float* gamma = (const float*)d_in[4];
    const float* beta  = (const float*)d_in[5];
    const float* mean  = (const float*)d_in[6];
    const float* var   = (const float*)d_in[7];
    float* out = (float*)d_out;

    static bool attr_set = false;
    if (!attr_set) {
        cudaFuncSetAttribute(conv_mma_kernel,
                             cudaFuncAttributeMaxDynamicSharedMemorySize, SMEM_SZ);
        attr_set = true;
    }

    prep_x_kernel<<<B_*CIN, 256>>>(x);
    gate_kernel<<<B_, 256>>>(gw, gb);
    prep_w_kernel<<<NCH, 256>>>(cw);
    conv_mma_kernel<<<Mtot/128, 256, SMEM_SZ>>>(gamma, beta, mean, var, out);
}

// round 6
// speedup vs baseline: 1.2054x; 1.2054x over previous
#include <cuda_runtime.h>
#include <cuda_bf16.h>
#include <cstdint>

#define B_    32
#define CIN   256
#define COUT  256
#define Hs    56
#define Ws    56
#define HW    3136
#define Mtot  100352
#define Kdim  2304
#define KZERO 128
#define NIMG  108          /* 64-k images: K'' / 64 */
#define CHPP  36           /* images per split-pass */
#define NCH2  54           /* 128-k chunks */
#define BTILE 32768        /* bytes per 64-k B image */

// ---------------- device scratch ----------------
__device__ float d_s[B_*CIN];
__device__ float d_t[B_*COUT];
__device__ __nv_bfloat16 d_xhi[(size_t)B_*CIN*HW];
__device__ __nv_bfloat16 d_xlo[(size_t)B_*CIN*HW];
__device__ __align__(16) __nv_bfloat16 d_bimg[(size_t)NIMG*256*64];

// ---------------------------------------------------------------------------
// P0: split x into bf16 hi/lo + abs-mean
// ---------------------------------------------------------------------------
__global__ void prep_x_kernel(const float* __restrict__ x) {
    int bc = blockIdx.x;
    size_t base = (size_t)bc * HW;
    float sum = 0.f;
    for (int j = threadIdx.x; j < HW; j += 256) {
        float v = x[base + j];
        __nv_bfloat16 h = __float2bfloat16(v);
        d_xhi[base + j] = h;
        d_xlo[base + j] = __float2bfloat16(v - __bfloat162float(h));
        sum += fabsf(v);
    }
    __shared__ float red[256];
    red[threadIdx.x] = sum;
    __syncthreads();
    for (int s = 128; s > 0; s >>= 1) {
        if (threadIdx.x < s) red[threadIdx.x] += red[threadIdx.x + s];
        __syncthreads();
    }
    if (threadIdx.x == 0) d_s[bc] = red[0] * (1.0f / HW);
}

// ---------------------------------------------------------------------------
// P1: pre-swizzled B images (row n: 128B = 64 bf16 along k, SW128)
// ---------------------------------------------------------------------------
__global__ void prep_w_kernel(const float* __restrict__ cw) {
    int c = blockIdx.x;
    int n = threadIdx.x;
    int p = (c >= 2*CHPP) ? 2 : (c >= CHPP ? 1 : 0);
    int kbase = c*64 - p*Kdim;
    char* dst = (char*)d_bimg + (size_t)c * BTILE;
    const float* wr = cw + (size_t)n * Kdim + kbase;
    for (int kk = 0; kk < 64; kk++) {
        float v = wr[kk];
        __nv_bfloat16 h = __float2bfloat16(v);
        __nv_bfloat16 val = (p == 1) ? __float2bfloat16(v - __bfloat162float(h)) : h;
        uint32_t off = (uint32_t)(n*128 + kk*2);
        off ^= (off >> 3) & 0x70;
        *(__nv_bfloat16*)(dst + off) = val;
    }
}

// ---------------------------------------------------------------------------
// P2: gate
// ---------------------------------------------------------------------------
__global__ void gate_kernel(const float* __restrict__ gw,
                            const float* __restrict__ gb) {
    int b = blockIdx.x;
    int c = threadIdx.x;
    __shared__ float s_sh[CIN];
    __shared__ float g_sh[COUT];
    __shared__ float red[256];

    s_sh[c] = d_s[b*CIN + c];
    __syncthreads();

    const float* wrow = gw + (size_t)c * CIN;
    float acc = gb[c];
    #pragma unroll 8
    for (int j = 0; j < CIN; j++) acc = fmaf(s_sh[j], wrow[j], acc);
    float g = fmaxf(acc, 0.f);
    g_sh[c] = g;
    __syncthreads();

    int rank = 0;
    for (int j = 0; j < COUT; j++) {
        float gj = g_sh[j];
        rank += (gj < g) || (gj == g && j < c);
    }
    float t = (rank < KZERO) ? 0.f : g;

    red[c] = t;
    __syncthreads();
    for (int s = 128; s > 0; s >>= 1) {
        if (c < s) red[c] += red[c + s];
        __syncthreads();
    }
    d_t[b*COUT + c] = t * ((float)COUT / red[0]);
}

// ---------------------------------------------------------------------------
// Main: mma.sync bf16 implicit GEMM.
// CTA 128m x 256n, 512 thr / 16 warps, warp tile 64x32, K-chunk 128
// (= two 64-k images), double-buffered; B via cp.async, A reg-prefetch gather.
// smem:
//   [0,65536)        A stages (2 x 32KB; each = two 16KB 64-k subtiles)
//   [65536,196608)   B stages (2 x 64KB; each = two contiguous images)
//   [196608,205824)  koff table (2304 u32)
//   [205824,206848)  inv_s[256]
//   [206848,207872)  add_s[256]
// ---------------------------------------------------------------------------
#define SM_A    0
#define SM_B    65536
#define SM_KOFF 196608
#define SM_INV  205824
#define SM_ADD  206848
#define SMEM_SZ 207872

__device__ __forceinline__ uint32_t smem_u32(const void* p) {
    uint32_t a;
    asm("{ .reg .u64 t; cvta.to.shared.u64 t, %1; cvt.u32.u64 %0, t; }" : "=r"(a) : "l"(p));
    return a;
}
__device__ __forceinline__ void ldmx4(uint32_t* r, uint32_t addr) {
    asm volatile("ldmatrix.sync.aligned.m8n8.x4.shared.b16 {%0,%1,%2,%3}, [%4];"
        : "=r"(r[0]), "=r"(r[1]), "=r"(r[2]), "=r"(r[3]) : "r"(addr));
}
__device__ __forceinline__ void mma16816(float* c, const uint32_t* a, const uint32_t* b) {
    asm volatile(
        "mma.sync.aligned.m16n8k16.row.col.f32.bf16.bf16.f32 "
        "{%0,%1,%2,%3}, {%4,%5,%6,%7}, {%8,%9}, {%0,%1,%2,%3};"
        : "+f"(c[0]), "+f"(c[1]), "+f"(c[2]), "+f"(c[3])
        : "r"(a[0]), "r"(a[1]), "r"(a[2]), "r"(a[3]), "r"(b[0]), "r"(b[1]));
}
__device__ __forceinline__ uint32_t sw128(uint32_t off) {
    return off ^ ((off >> 3) & 0x70);
}
__device__ __forceinline__ void cp16(uint32_t saddr, const void* g) {
    asm volatile("cp.async.cg.shared.global [%0], [%1], 16;" :: "r"(saddr), "l"(g) : "memory");
}
#define CP_COMMIT() asm volatile("cp.async.commit_group;" ::: "memory")
#define CP_WAIT0()  asm volatile("cp.async.wait_group 0;" ::: "memory")

__global__ void __launch_bounds__(512, 1)
conv_mma_kernel(const float* __restrict__ gamma, const float* __restrict__ beta,
                const float* __restrict__ mean,  const float* __restrict__ var,
                float* __restrict__ out)
{
    extern __shared__ __align__(1024) char smem[];
    uint32_t* koff_s = (uint32_t*)(smem + SM_KOFF);
    float* inv_s = (float*)(smem + SM_INV);
    float* add_s = (float*)(smem + SM_ADD);
    const uint32_t su = smem_u32(smem);

    const int t = threadIdx.x;
    const int lane = t & 31;
    const int wrp = t >> 5;            // 0..15
    const int wm = (wrp & 1) * 64;     // warp m offset
    const int wn = (wrp >> 1) * 32;    // warp n offset

    // koff table: k -> (rs<<20) | (offset+64)
    for (int k = t; k < Kdim; k += 512) {
        int ci = k / 9, rs = k - ci*9;
        int dh = rs / 3, dw = rs - dh*3;
        int off = ci*HW + (dh-1)*Ws + (dw-1);
        koff_s[k] = ((uint32_t)rs << 20) | (uint32_t)(off + 64);
    }
    if (t < 256) {
        float iv = gamma[t] * rsqrtf(var[t] + 1e-5f);
        inv_s[t] = iv;
        add_s[t] = beta[t] - mean[t]*iv;
    }
    __syncthreads();   // koff_s ready before prologue gather

    // ---- A loader geometry: 4 threads per m-row; each owns 8 k-groups ----
    const int mtile = blockIdx.x * 128;
    const int r = t & 127;
    const int kqb = (t >> 7) * 8;      // first k-group (of 4 values), 0/8/16/24
    const int m = mtile + r;
    const int bb = m / HW;
    const int rem = m - bb*HW;
    const int hh = rem / Ws;
    const int ww = rem - hh*Ws;
    const int boff = bb*(CIN*HW) + hh*Ws + ww;
    int msk = 0;
    #pragma unroll
    for (int rs = 0; rs < 9; rs++) {
        int dh = rs/3, dw = rs - dh*3;
        int hy = hh + dh - 1, wx = ww + dw - 1;
        if ((unsigned)hy < Hs && (unsigned)wx < Ws) msk |= (1 << rs);
    }
    // store offsets: subtile (kq>>4)*16384 + sw128(r*128 + (kq&15)*8)
    uint32_t stA[8];
    #pragma unroll
    for (int q = 0; q < 8; q++) {
        int kq = kqb + q;
        stA[q] = (uint32_t)((kq >> 4) * 16384) + sw128((uint32_t)(r*128 + (kq & 15)*8));
    }

    // ldmatrix lane geometry
    const int a_row = (lane & 15);
    const int a_kb  = (lane & 16) ? 16 : 0;
    const int b_row = ((lane & 16) ? 8 : 0) + (lane & 7);
    const int b_kb  = (lane & 8) ? 16 : 0;

    const unsigned short* xhi = (const unsigned short*)d_xhi;
    const unsigned short* xlo = (const unsigned short*)d_xlo;
    const char* bsrc = (const char*)d_bimg;

    float acc[4][4][4];
    #pragma unroll
    for (int i = 0; i < 4; i++)
        #pragma unroll
        for (int j = 0; j < 4; j++)
            #pragma unroll
            for (int q = 0; q < 4; q++) acc[i][j][q] = 0.f;

    // ---- prologue: chunk 0 into stage 0 ----
    {
        #pragma unroll
        for (int q = 0; q < 8; q++)
            cp16(su + SM_B + (uint32_t)(q*512 + t)*16, bsrc + (q*512 + t)*16);
        CP_COMMIT();
        char* abase = smem + SM_A;
        #pragma unroll
        for (int q = 0; q < 8; q++) {
            uint4 e = *(const uint4*)(koff_s + (kqb + q)*4);
            uint32_t v0 = ((msk >> (e.x >> 20)) & 1) ? (uint32_t)xhi[boff + (int)(e.x & 0xFFFFFu) - 64] : 0u;
            uint32_t v1 = ((msk >> (e.y >> 20)) & 1) ? (uint32_t)xhi[boff + (int)(e.y & 0xFFFFFu) - 64] : 0u;
            uint32_t v2 = ((msk >> (e.z >> 20)) & 1) ? (uint32_t)xhi[boff + (int)(e.z & 0xFFFFFu) - 64] : 0u;
            uint32_t v3 = ((msk >> (e.w >> 20)) & 1) ? (uint32_t)xhi[boff + (int)(e.w & 0xFFFFFu) - 64] : 0u;
            *(uint2*)(abase + stA[q]) = make_uint2(v0 | (v1 << 16), v2 | (v3 << 16));
        }
        CP_WAIT0();
    }
    __syncthreads();

    for (int c = 0; c < NCH2; c++) {
        const int buf = c & 1;
        const bool more = (c + 1 < NCH2);

        // ---- issue next-chunk loads ----
        uint2 sA[8];
        if (more) {
            const int cn = c + 1;
            const char* src = bsrc + (size_t)cn * 65536;
            const uint32_t bdst = su + SM_B + (uint32_t)(buf^1)*65536;
            #pragma unroll
            for (int q = 0; q < 8; q++)
                cp16(bdst + (uint32_t)(q*512 + t)*16, src + (q*512 + t)*16);
            CP_COMMIT();
            const int p = (cn >= 36) ? 2 : (cn >= 18 ? 1 : 0);
            const unsigned short* sx = (p == 2) ? xlo : xhi;
            const int k0 = cn*128 - p*Kdim;
            #pragma unroll
            for (int q = 0; q < 8; q++) {
                uint4 e = *(const uint4*)(koff_s + k0 + (kqb + q)*4);
                uint32_t v0 = ((msk >> (e.x >> 20)) & 1) ? (uint32_t)sx[boff + (int)(e.x & 0xFFFFFu) - 64] : 0u;
                uint32_t v1 = ((msk >> (e.y >> 20)) & 1) ? (uint32_t)sx[boff + (int)(e.y & 0xFFFFFu) - 64] : 0u;
                uint32_t v2 = ((msk >> (e.z >> 20)) & 1) ? (uint32_t)sx[boff + (int)(e.z & 0xFFFFFu) - 64] : 0u;
                uint32_t v3 = ((msk >> (e.w >> 20)) & 1) ? (uint32_t)sx[boff + (int)(e.w & 0xFFFFFu) - 64] : 0u;
                sA[q] = make_uint2(v0 | (v1 << 16), v2 | (v3 << 16));
            }
        }

        // ---- compute 8 k16 steps from stage buf ----
        const uint32_t Ab = su + SM_A + buf*32768;
        const uint32_t Bb = su + SM_B + buf*65536;
        #pragma unroll
        for (int ks = 0; ks < 8; ks++) {
            const uint32_t Asub = Ab + (ks >> 2)*16384;
            const uint32_t Bsub = Bb + (ks >> 2)*32768;
            const int kloc = ks & 3;
            uint32_t af[4][4];
            #pragma unroll
            for (int am = 0; am < 4; am++) {
                uint32_t off = (uint32_t)((wm + am*16 + a_row)*128 + kloc*32 + a_kb);
                ldmx4(af[am], Asub + sw128(off));
            }
            uint32_t bf[4][2];
            #pragma unroll
            for (int bp = 0; bp < 2; bp++) {
                uint32_t rr[4];
                uint32_t off = (uint32_t)((wn + bp*16 + b_row)*128 + kloc*32 + b_kb);
                ldmx4(rr, Bsub + sw128(off));
                bf[2*bp][0] = rr[0]; bf[2*bp][1] = rr[1];
                bf[2*bp+1][0] = rr[2]; bf[2*bp+1][1] = rr[3];
            }
            #pragma unroll
            for (int am = 0; am < 4; am++)
                #pragma unroll
                for (int bn = 0; bn < 4; bn++)
                    mma16816(acc[am][bn], af[am], bf[bn]);
        }

        // ---- drain staged A, wait B cp.async, flip ----
        if (more) {
            char* abase = smem + SM_A + (buf^1)*32768;
            #pragma unroll
            for (int q = 0; q < 8; q++)
                *(uint2*)(abase + stA[q]) = sA[q];
            CP_WAIT0();
        }
        __syncthreads();
    }

    // ---- epilogue: BN + ReLU + gate, write NCHW ----
    #pragma unroll
    for (int am = 0; am < 4; am++) {
        int mr0 = mtile + wm + am*16 + (lane >> 2);
        #pragma unroll
        for (int half = 0; half < 2; half++) {
            int mr = mr0 + half*8;
            int b = mr / HW;
            int rm = mr - b*HW;
            float* op = out + (size_t)b*(COUT*HW) + rm;
            const float* tp = d_t + b*COUT;
            #pragma unroll
            for (int bn = 0; bn < 4; bn++) {
                int n = wn + bn*8 + 2*(lane & 3);
                float v0 = fmaf(acc[am][bn][half*2+0], inv_s[n],   add_s[n]);
                float v1 = fmaf(acc[am][bn][half*2+1], inv_s[n+1], add_s[n+1]);
                v0 = fmaxf(v0, 0.f) * __ldg(tp + n);
                v1 = fmaxf(v1, 0.f) * __ldg(tp + n + 1);
                op[(size_t)n * HW] = v0;
                op[(size_t)(n+1) * HW] = v1;
            }
        }
    }
}

// ---------------------------------------------------------------------------
extern "C" void kernel_launch(void* const* d_in, const int* in_sizes, int n_in,
                              void* d_out, int out_size) {
    const float* x     = (const float*)d_in[0];
    const float* cw    = (const float*)d_in[1];
    const float* gw    = (const float*)d_in[2];
    const float* gb    = (const float*)d_in[3];
    const float* gamma = (const float*)d_in[4];
    const float* beta  = (const float*)d_in[5];
    const float* mean  = (const float*)d_in[6];
    const float* var   = (const float*)d_in[7];
    float* out = (float*)d_out;

    static bool attr_set = false;
    if (!attr_set) {
        cudaFuncSetAttribute(conv_mma_kernel,
                             cudaFuncAttributeMaxDynamicSharedMemorySize, SMEM_SZ);
        attr_set = true;
    }

    prep_x_kernel<<<B_*CIN, 256>>>(x);
    gate_kernel<<<B_, 256>>>(gw, gb);
    prep_w_kernel<<<NIMG, 256>>>(cw);
    conv_mma_kernel<<<Mtot/128, 512, SMEM_SZ>>>(gamma, beta, mean, var, out);
}

// round 7
// speedup vs baseline: 1.2714x; 1.0548x over previous
#include <cuda_runtime.h>
#include <cuda_bf16.h>
#include <cstdint>

#define B_    32
#define CIN   256
#define COUT  256
#define Hs    56
#define Ws    56
#define HW    3136
#define Kdim  2304
#define KZERO 128
#define NIMG  108          /* 64-k images: K'' / 64 */
#define CHPP  36           /* images per split-pass */
#define BTILE 32768        /* bytes per 64-k B image (256 n) */
#define PADW  57           /* padded row width */
#define SLAB  3368         /* elems per (b,ci) padded slab (59*57=3363 ->pad 8) */
#define MPB   3192         /* 56*57 m' per batch */
#define TPB   25           /* m'-tiles of 128 per batch */

// ---------------- device scratch ----------------
__device__ float d_s[B_*CIN];
__device__ float d_t[B_*COUT];
__device__ __nv_bfloat16 d_xhi[(size_t)B_*CIN*SLAB];
__device__ __nv_bfloat16 d_xlo[(size_t)B_*CIN*SLAB];
__device__ __align__(16) __nv_bfloat16 d_bimg[(size_t)NIMG*256*64];

// ---------------------------------------------------------------------------
// P0: padded bf16 hi/lo slabs + abs-mean
// ---------------------------------------------------------------------------
__global__ void prep_x_kernel(const float* __restrict__ x) {
    int bc = blockIdx.x;
    const float* xs = x + (size_t)bc * HW;
    size_t sb = (size_t)bc * SLAB;
    for (int j = threadIdx.x; j < SLAB; j += 256) {
        d_xhi[sb + j] = __float2bfloat16(0.f);
        d_xlo[sb + j] = __float2bfloat16(0.f);
    }
    __syncthreads();
    float sum = 0.f;
    for (int j = threadIdx.x; j < HW; j += 256) {
        float v = xs[j];
        __nv_bfloat16 h = __float2bfloat16(v);
        int hy = j / Ws, wx = j - hy*Ws;
        int pi = (hy+1)*PADW + wx + 1;
        d_xhi[sb + pi] = h;
        d_xlo[sb + pi] = __float2bfloat16(v - __bfloat162float(h));
        sum += fabsf(v);
    }
    __shared__ float red[256];
    red[threadIdx.x] = sum;
    __syncthreads();
    for (int s = 128; s > 0; s >>= 1) {
        if (threadIdx.x < s) red[threadIdx.x] += red[threadIdx.x + s];
        __syncthreads();
    }
    if (threadIdx.x == 0) d_s[bc] = red[0] * (1.0f / HW);
}

// ---------------------------------------------------------------------------
// P1: pre-swizzled B images (row n: 128B = 64 bf16 along k, SW128)
// ---------------------------------------------------------------------------
__global__ void prep_w_kernel(const float* __restrict__ cw) {
    int c = blockIdx.x;
    int n = threadIdx.x;
    int p = (c >= 2*CHPP) ? 2 : (c >= CHPP ? 1 : 0);
    int kbase = c*64 - p*Kdim;
    char* dst = (char*)d_bimg + (size_t)c * BTILE;
    const float* wr = cw + (size_t)n * Kdim + kbase;
    for (int kk = 0; kk < 64; kk++) {
        float v = wr[kk];
        __nv_bfloat16 h = __float2bfloat16(v);
        __nv_bfloat16 val = (p == 1) ? __float2bfloat16(v - __bfloat162float(h)) : h;
        uint32_t off = (uint32_t)(n*128 + kk*2);
        off ^= (off >> 3) & 0x70;
        *(__nv_bfloat16*)(dst + off) = val;
    }
}

// ---------------------------------------------------------------------------
// P2: gate
// ---------------------------------------------------------------------------
__global__ void gate_kernel(const float* __restrict__ gw,
                            const float* __restrict__ gb) {
    int b = blockIdx.x;
    int c = threadIdx.x;
    __shared__ float s_sh[CIN];
    __shared__ float g_sh[COUT];
    __shared__ float red[256];

    s_sh[c] = d_s[b*CIN + c];
    __syncthreads();

    const float* wrow = gw + (size_t)c * CIN;
    float acc = gb[c];
    #pragma unroll 8
    for (int j = 0; j < CIN; j++) acc = fmaf(s_sh[j], wrow[j], acc);
    float g = fmaxf(acc, 0.f);
    g_sh[c] = g;
    __syncthreads();

    int rank = 0;
    for (int j = 0; j < COUT; j++) {
        float gj = g_sh[j];
        rank += (gj < g) || (gj == g && j < c);
    }
    float t = (rank < KZERO) ? 0.f : g;

    red[c] = t;
    __syncthreads();
    for (int s = 128; s > 0; s >>= 1) {
        if (c < s) red[c] += red[c + s];
        __syncthreads();
    }
    d_t[b*COUT + c] = t * ((float)COUT / red[0]);
}

// ---------------------------------------------------------------------------
// Main: mma.sync bf16 implicit GEMM, 2 CTAs/SM.
// CTA 128m x 128n, 256 thr / 8 warps, warp tile 64x32, 64-k chunks.
// A: padded-slab LDG reg-prefetch (no masks), double-buffered smem.
// B: 4-stage cp.async ring from pre-swizzled images (n-half per CTA).
// smem:
//   [0,32768)        A (2 x 16KB)
//   [32768,98304)    B (4 x 16KB)
//   [98304,107520)   koff table (2304 u32)
//   [107520,108544)  inv_s[256]
//   [108544,109568)  add_s[256]
// ---------------------------------------------------------------------------
#define SM_A    0
#define SM_B    32768
#define SM_KOFF 98304
#define SM_INV  107520
#define SM_ADD  108544
#define SMEM_SZ 109568

__device__ __forceinline__ uint32_t smem_u32(const void* p) {
    uint32_t a;
    asm("{ .reg .u64 t; cvta.to.shared.u64 t, %1; cvt.u32.u64 %0, t; }" : "=r"(a) : "l"(p));
    return a;
}
__device__ __forceinline__ void ldmx4(uint32_t* r, uint32_t addr) {
    asm volatile("ldmatrix.sync.aligned.m8n8.x4.shared.b16 {%0,%1,%2,%3}, [%4];"
        : "=r"(r[0]), "=r"(r[1]), "=r"(r[2]), "=r"(r[3]) : "r"(addr));
}
__device__ __forceinline__ void mma16816(float* c, const uint32_t* a, const uint32_t* b) {
    asm volatile(
        "mma.sync.aligned.m16n8k16.row.col.f32.bf16.bf16.f32 "
        "{%0,%1,%2,%3}, {%4,%5,%6,%7}, {%8,%9}, {%0,%1,%2,%3};"
        : "+f"(c[0]), "+f"(c[1]), "+f"(c[2]), "+f"(c[3])
        : "r"(a[0]), "r"(a[1]), "r"(a[2]), "r"(a[3]), "r"(b[0]), "r"(b[1]));
}
__device__ __forceinline__ uint32_t sw128(uint32_t off) {
    return off ^ ((off >> 3) & 0x70);
}
__device__ __forceinline__ void cp16(uint32_t saddr, const void* g) {
    asm volatile("cp.async.cg.shared.global [%0], [%1], 16;" :: "r"(saddr), "l"(g) : "memory");
}
#define CP_COMMIT() asm volatile("cp.async.commit_group;" ::: "memory")
#define CP_WAIT2()  asm volatile("cp.async.wait_group 2;" ::: "memory")

__global__ void __launch_bounds__(256, 2)
conv_mma_kernel(const float* __restrict__ gamma, const float* __restrict__ beta,
                const float* __restrict__ mean,  const float* __restrict__ var,
                float* __restrict__ out)
{
    extern __shared__ __align__(1024) char smem[];
    uint32_t* koff_s = (uint32_t*)(smem + SM_KOFF);
    float* inv_s = (float*)(smem + SM_INV);
    float* add_s = (float*)(smem + SM_ADD);
    const uint32_t su = smem_u32(smem);

    const int t = threadIdx.x;
    const int lane = t & 31;
    const int wrp = t >> 5;            // 0..7
    const int wm = (wrp & 1) * 64;
    const int wn = (wrp >> 1) * 32;    // n offset within 128-half

    const int nh = blockIdx.x;                 // n half: 0/1
    const int by = blockIdx.y;
    const int b  = by / TPB;
    const int tile = by - b*TPB;

    // koff table: k -> slab-relative offset
    for (int k = t; k < Kdim; k += 256) {
        int ci = k / 9, rs = k - ci*9;
        int dh = rs / 3, dw = rs - dh*3;
        koff_s[k] = (uint32_t)(ci*SLAB + dh*PADW + dw);
    }
    {
        float iv = gamma[t] * rsqrtf(var[t] + 1e-5f);
        inv_s[t] = iv;
        add_s[t] = beta[t] - mean[t]*iv;
    }
    __syncthreads();

    // ---- A loader geometry: 2 threads per m-row, each 8 k-groups of 4 ----
    const int r = t & 127;
    const int kqb = (t >> 7) * 8;      // 0 or 8
    const unsigned short* xbase_hi = (const unsigned short*)d_xhi
        + (size_t)b * (CIN*SLAB) + tile*128 + r;
    const unsigned short* xbase_lo = (const unsigned short*)d_xlo
        + (size_t)b * (CIN*SLAB) + tile*128 + r;
    uint32_t stA[8];
    #pragma unroll
    for (int q = 0; q < 8; q++)
        stA[q] = sw128((uint32_t)(r*128 + (kqb + q)*8));

    // ldmatrix lane geometry
    const int a_row = (lane & 15);
    const int a_kb  = (lane & 16) ? 16 : 0;
    const int b_row = ((lane & 16) ? 8 : 0) + (lane & 7);
    const int b_kb  = (lane & 8) ? 16 : 0;

    const char* bsrc = (const char*)d_bimg + (size_t)nh * 16384;

    float acc[4][4][4];
    #pragma unroll
    for (int i = 0; i < 4; i++)
        #pragma unroll
        for (int j = 0; j < 4; j++)
            #pragma unroll
            for (int q = 0; q < 4; q++) acc[i][j][q] = 0.f;

    // ---- prologue ----
    // B: issue chunks 0,1,2 into stages 0,1,2
    #pragma unroll
    for (int pc = 0; pc < 3; pc++) {
        const char* src = bsrc + (size_t)pc * BTILE;
        uint32_t dst = su + SM_B + pc*16384;
        #pragma unroll
        for (int q = 0; q < 4; q++)
            cp16(dst + (uint32_t)(q*256 + t)*16, src + (q*256 + t)*16);
        CP_COMMIT();
    }
    // A chunk 0 -> buf 0
    {
        char* abase = smem + SM_A;
        #pragma unroll
        for (int q = 0; q < 8; q++) {
            uint4 e = *(const uint4*)(koff_s + (kqb + q)*4);
            uint32_t v0 = xbase_hi[e.x];
            uint32_t v1 = xbase_hi[e.y];
            uint32_t v2 = xbase_hi[e.z];
            uint32_t v3 = xbase_hi[e.w];
            *(uint2*)(abase + stA[q]) = make_uint2(v0 | (v1 << 16), v2 | (v3 << 16));
        }
    }
    CP_WAIT2();            // stage 0 complete
    __syncthreads();

    for (int c = 0; c < NIMG; c++) {
        const int buf = c & 1;
        const int bstage = c & 3;
        const bool more = (c + 1 < NIMG);

        // ---- B prefetch c+3 (empty commit keeps wait arithmetic uniform) ----
        if (c + 3 < NIMG) {
            const char* src = bsrc + (size_t)(c+3) * BTILE;
            uint32_t dst = su + SM_B + ((c+3) & 3)*16384;
            #pragma unroll
            for (int q = 0; q < 4; q++)
                cp16(dst + (uint32_t)(q*256 + t)*16, src + (q*256 + t)*16);
        }
        CP_COMMIT();

        // ---- A prefetch c+1 into regs ----
        uint2 sA[8];
        if (more) {
            const int cn = c + 1;
            const int p = (cn >= 2*CHPP) ? 2 : (cn >= CHPP ? 1 : 0);
            const unsigned short* sx = (p == 2) ? xbase_lo : xbase_hi;
            const int k0 = cn*64 - p*Kdim;
            #pragma unroll
            for (int q = 0; q < 8; q++) {
                uint4 e = *(const uint4*)(koff_s + k0 + (kqb + q)*4);
                uint32_t v0 = sx[e.x];
                uint32_t v1 = sx[e.y];
                uint32_t v2 = sx[e.z];
                uint32_t v3 = sx[e.w];
                sA[q] = make_uint2(v0 | (v1 << 16), v2 | (v3 << 16));
            }
        }

        // ---- compute 4 k16 steps ----
        const uint32_t Ab = su + SM_A + buf*16384;
        const uint32_t Bb = su + SM_B + bstage*16384;
        #pragma unroll
        for (int ks = 0; ks < 4; ks++) {
            uint32_t af[4][4];
            #pragma unroll
            for (int am = 0; am < 4; am++) {
                uint32_t off = (uint32_t)((wm + am*16 + a_row)*128 + ks*32 + a_kb);
                ldmx4(af[am], Ab + sw128(off));
            }
            uint32_t bf[4][2];
            #pragma unroll
            for (int bp = 0; bp < 2; bp++) {
                uint32_t rr[4];
                uint32_t off = (uint32_t)((wn + bp*16 + b_row)*128 + ks*32 + b_kb);
                ldmx4(rr, Bb + sw128(off));
                bf[2*bp][0] = rr[0]; bf[2*bp][1] = rr[1];
                bf[2*bp+1][0] = rr[2]; bf[2*bp+1][1] = rr[3];
            }
            #pragma unroll
            for (int am = 0; am < 4; am++)
                #pragma unroll
                for (int bn = 0; bn < 4; bn++)
                    mma16816(acc[am][bn], af[am], bf[bn]);
        }

        // ---- drain staged A, ensure B(c+1) landed, flip ----
        if (more) {
            char* abase = smem + SM_A + (buf^1)*16384;
            #pragma unroll
            for (int q = 0; q < 8; q++)
                *(uint2*)(abase + stA[q]) = sA[q];
        }
        CP_WAIT2();
        __syncthreads();
    }

    // ---- epilogue: BN + ReLU + gate, predicated NCHW store ----
    const float* tp = d_t + b*COUT;
    #pragma unroll
    for (int am = 0; am < 4; am++) {
        int mr0 = tile*128 + wm + am*16 + (lane >> 2);
        #pragma unroll
        for (int half = 0; half < 2; half++) {
            int mp = mr0 + half*8;          // m' in padded geometry
            int h = mp / PADW;
            int w = mp - h*PADW;
            bool valid = (h < Hs) && (w < Ws);
            float* op = out + (size_t)b*(COUT*HW) + h*Ws + w;
            #pragma unroll
            for (int bn = 0; bn < 4; bn++) {
                int n = nh*128 + wn + bn*8 + 2*(lane & 3);
                float v0 = fmaf(acc[am][bn][half*2+0], inv_s[n],   add_s[n]);
                float v1 = fmaf(acc[am][bn][half*2+1], inv_s[n+1], add_s[n+1]);
                v0 = fmaxf(v0, 0.f) * __ldg(tp + n);
                v1 = fmaxf(v1, 0.f) * __ldg(tp + n + 1);
                if (valid) {
                    op[(size_t)n * HW] = v0;
                    op[(size_t)(n+1) * HW] = v1;
                }
            }
        }
    }
}

// ---------------------------------------------------------------------------
extern "C" void kernel_launch(void* const* d_in, const int* in_sizes, int n_in,
                              void* d_out, int out_size) {
    const float* x     = (const float*)d_in[0];
    const float* cw    = (const float*)d_in[1];
    const float* gw    = (const float*)d_in[2];
    const float* gb    = (const float*)d_in[3];
    const float* gamma = (const float*)d_in[4];
    const float* beta  = (const float*)d_in[5];
    const float* mean  = (const float*)d_in[6];
    const float* var   = (const float*)d_in[7];
    float* out = (float*)d_out;

    static bool attr_set = false;
    if (!attr_set) {
        cudaFuncSetAttribute(conv_mma_kernel,
                             cudaFuncAttributeMaxDynamicSharedMemorySize, SMEM_SZ);
        attr_set = true;
    }

    prep_x_kernel<<<B_*CIN, 256>>>(x);
    gate_kernel<<<B_, 256>>>(gw, gb);
    prep_w_kernel<<<NIMG, 256>>>(cw);
    dim3 grid(2, B_*TPB);
    conv_mma_kernel<<<grid, 256, SMEM_SZ>>>(gamma, beta, mean, var, out);
}

// round 8
// speedup vs baseline: 2.9898x; 2.3515x over previous
#include <cuda_runtime.h>
#include <cuda_fp16.h>
#include <cstdint>

#define B_    32
#define CIN   256
#define COUT  256
#define Hs    56
#define Ws    56
#define HW    3136
#define Kdim  2304
#define KZERO 128
#define NIMG  36           /* 64-k images: Kdim/64 (single fp16 pass) */
#define BTILE 32768        /* bytes per 64-k B image (256 n) */
#define PADW  57
#define SLAB  3368         /* elems per (b,ci) padded slab */
#define TPB   25           /* m'-tiles of 128 per batch */

// ---------------- device scratch ----------------
__device__ float d_s[B_*CIN];
__device__ float d_t[B_*COUT];
__device__ __half d_xh[(size_t)B_*CIN*SLAB];
__device__ __align__(16) __half d_bimg[(size_t)NIMG*256*64];

// ---------------------------------------------------------------------------
// P0: padded fp16 slab + abs-mean
// ---------------------------------------------------------------------------
__global__ void prep_x_kernel(const float* __restrict__ x) {
    int bc = blockIdx.x;
    const float* xs = x + (size_t)bc * HW;
    size_t sb = (size_t)bc * SLAB;
    for (int j = threadIdx.x; j < SLAB; j += 256)
        d_xh[sb + j] = __float2half(0.f);
    __syncthreads();
    float sum = 0.f;
    for (int j = threadIdx.x; j < HW; j += 256) {
        float v = xs[j];
        int hy = j / Ws, wx = j - hy*Ws;
        d_xh[sb + (hy+1)*PADW + wx + 1] = __float2half(v);
        sum += fabsf(v);
    }
    __shared__ float red[256];
    red[threadIdx.x] = sum;
    __syncthreads();
    for (int s = 128; s > 0; s >>= 1) {
        if (threadIdx.x < s) red[threadIdx.x] += red[threadIdx.x + s];
        __syncthreads();
    }
    if (threadIdx.x == 0) d_s[bc] = red[0] * (1.0f / HW);
}

// ---------------------------------------------------------------------------
// P1: pre-swizzled fp16 B images (row n: 128B = 64 fp16 along k, SW128)
// ---------------------------------------------------------------------------
__global__ void prep_w_kernel(const float* __restrict__ cw) {
    int c = blockIdx.x;
    int n = threadIdx.x;
    int kbase = c*64;
    char* dst = (char*)d_bimg + (size_t)c * BTILE;
    const float* wr = cw + (size_t)n * Kdim + kbase;
    for (int kk = 0; kk < 64; kk++) {
        uint32_t off = (uint32_t)(n*128 + kk*2);
        off ^= (off >> 3) & 0x70;
        *(__half*)(dst + off) = __float2half(wr[kk]);
    }
}

// ---------------------------------------------------------------------------
// P2: gate
// ---------------------------------------------------------------------------
__global__ void gate_kernel(const float* __restrict__ gw,
                            const float* __restrict__ gb) {
    int b = blockIdx.x;
    int c = threadIdx.x;
    __shared__ float s_sh[CIN];
    __shared__ float g_sh[COUT];
    __shared__ float red[256];

    s_sh[c] = d_s[b*CIN + c];
    __syncthreads();

    const float* wrow = gw + (size_t)c * CIN;
    float acc = gb[c];
    #pragma unroll 8
    for (int j = 0; j < CIN; j++) acc = fmaf(s_sh[j], wrow[j], acc);
    float g = fmaxf(acc, 0.f);
    g_sh[c] = g;
    __syncthreads();

    int rank = 0;
    for (int j = 0; j < COUT; j++) {
        float gj = g_sh[j];
        rank += (gj < g) || (gj == g && j < c);
    }
    float t = (rank < KZERO) ? 0.f : g;

    red[c] = t;
    __syncthreads();
    for (int s = 128; s > 0; s >>= 1) {
        if (c < s) red[c] += red[c + s];
        __syncthreads();
    }
    d_t[b*COUT + c] = t * ((float)COUT / red[0]);
}

// ---------------------------------------------------------------------------
// Main: mma.sync fp16 implicit GEMM, 2 CTAs/SM.
// CTA 128m x 128n, 256 thr / 8 warps, warp tile 64x32, 64-k chunks (36).
// A: padded-slab LDG reg-prefetch, double-buffered smem.
// B: 4-stage cp.async ring from pre-swizzled images (n-half per CTA).
// ---------------------------------------------------------------------------
#define SM_A    0
#define SM_B    32768
#define SM_KOFF 98304
#define SM_INV  107520
#define SM_ADD  108544
#define SMEM_SZ 109568

__device__ __forceinline__ uint32_t smem_u32(const void* p) {
    uint32_t a;
    asm("{ .reg .u64 t; cvta.to.shared.u64 t, %1; cvt.u32.u64 %0, t; }" : "=r"(a) : "l"(p));
    return a;
}
__device__ __forceinline__ void ldmx4(uint32_t* r, uint32_t addr) {
    asm volatile("ldmatrix.sync.aligned.m8n8.x4.shared.b16 {%0,%1,%2,%3}, [%4];"
        : "=r"(r[0]), "=r"(r[1]), "=r"(r[2]), "=r"(r[3]) : "r"(addr));
}
__device__ __forceinline__ void mma16816(float* c, const uint32_t* a, const uint32_t* b) {
    asm volatile(
        "mma.sync.aligned.m16n8k16.row.col.f32.f16.f16.f32 "
        "{%0,%1,%2,%3}, {%4,%5,%6,%7}, {%8,%9}, {%0,%1,%2,%3};"
        : "+f"(c[0]), "+f"(c[1]), "+f"(c[2]), "+f"(c[3])
        : "r"(a[0]), "r"(a[1]), "r"(a[2]), "r"(a[3]), "r"(b[0]), "r"(b[1]));
}
__device__ __forceinline__ uint32_t sw128(uint32_t off) {
    return off ^ ((off >> 3) & 0x70);
}
__device__ __forceinline__ void cp16(uint32_t saddr, const void* g) {
    asm volatile("cp.async.cg.shared.global [%0], [%1], 16;" :: "r"(saddr), "l"(g) : "memory");
}
#define CP_COMMIT() asm volatile("cp.async.commit_group;" ::: "memory")
#define CP_WAIT2()  asm volatile("cp.async.wait_group 2;" ::: "memory")

__global__ void __launch_bounds__(256, 2)
conv_mma_kernel(const float* __restrict__ gamma, const float* __restrict__ beta,
                const float* __restrict__ mean,  const float* __restrict__ var,
                float* __restrict__ out)
{
    extern __shared__ __align__(1024) char smem[];
    uint32_t* koff_s = (uint32_t*)(smem + SM_KOFF);
    float* inv_s = (float*)(smem + SM_INV);
    float* add_s = (float*)(smem + SM_ADD);
    const uint32_t su = smem_u32(smem);

    const int t = threadIdx.x;
    const int lane = t & 31;
    const int wrp = t >> 5;
    const int wm = (wrp & 1) * 64;
    const int wn = (wrp >> 1) * 32;

    const int nh = blockIdx.x;                 // n half: 0/1
    const int by = blockIdx.y;
    const int b  = by / TPB;
    const int tile = by - b*TPB;

    for (int k = t; k < Kdim; k += 256) {
        int ci = k / 9, rs = k - ci*9;
        int dh = rs / 3, dw = rs - dh*3;
        koff_s[k] = (uint32_t)(ci*SLAB + dh*PADW + dw);
    }
    {
        float iv = gamma[t] * rsqrtf(var[t] + 1e-5f);
        inv_s[t] = iv;
        add_s[t] = beta[t] - mean[t]*iv;
    }
    __syncthreads();

    // ---- A loader geometry ----
    const int r = t & 127;
    const int kqb = (t >> 7) * 8;      // 0 or 8
    const unsigned short* xbase = (const unsigned short*)d_xh
        + (size_t)b * (CIN*SLAB) + tile*128 + r;
    uint32_t stA[8];
    #pragma unroll
    for (int q = 0; q < 8; q++)
        stA[q] = sw128((uint32_t)(r*128 + (kqb + q)*8));

    // ldmatrix lane geometry
    const int a_row = (lane & 15);
    const int a_kb  = (lane & 16) ? 16 : 0;
    const int b_row = ((lane & 16) ? 8 : 0) + (lane & 7);
    const int b_kb  = (lane & 8) ? 16 : 0;

    const char* bsrc = (const char*)d_bimg + (size_t)nh * 16384;

    float acc[4][4][4];
    #pragma unroll
    for (int i = 0; i < 4; i++)
        #pragma unroll
        for (int j = 0; j < 4; j++)
            #pragma unroll
            for (int q = 0; q < 4; q++) acc[i][j][q] = 0.f;

    // ---- prologue: B stages 0..2, A chunk 0 ----
    #pragma unroll
    for (int pc = 0; pc < 3; pc++) {
        const char* src = bsrc + (size_t)pc * BTILE;
        uint32_t dst = su + SM_B + pc*16384;
        #pragma unroll
        for (int q = 0; q < 4; q++)
            cp16(dst + (uint32_t)(q*256 + t)*16, src + (q*256 + t)*16);
        CP_COMMIT();
    }
    {
        char* abase = smem + SM_A;
        #pragma unroll
        for (int q = 0; q < 8; q++) {
            uint4 e = *(const uint4*)(koff_s + (kqb + q)*4);
            uint32_t v0 = xbase[e.x];
            uint32_t v1 = xbase[e.y];
            uint32_t v2 = xbase[e.z];
            uint32_t v3 = xbase[e.w];
            *(uint2*)(abase + stA[q]) = make_uint2(v0 | (v1 << 16), v2 | (v3 << 16));
        }
    }
    CP_WAIT2();
    __syncthreads();

    for (int c = 0; c < NIMG; c++) {
        const int buf = c & 1;
        const int bstage = c & 3;
        const bool more = (c + 1 < NIMG);

        if (c + 3 < NIMG) {
            const char* src = bsrc + (size_t)(c+3) * BTILE;
            uint32_t dst = su + SM_B + ((c+3) & 3)*16384;
            #pragma unroll
            for (int q = 0; q < 4; q++)
                cp16(dst + (uint32_t)(q*256 + t)*16, src + (q*256 + t)*16);
        }
        CP_COMMIT();

        uint2 sA[8];
        if (more) {
            const int k0 = (c + 1)*64;
            #pragma unroll
            for (int q = 0; q < 8; q++) {
                uint4 e = *(const uint4*)(koff_s + k0 + (kqb + q)*4);
                uint32_t v0 = xbase[e.x];
                uint32_t v1 = xbase[e.y];
                uint32_t v2 = xbase[e.z];
                uint32_t v3 = xbase[e.w];
                sA[q] = make_uint2(v0 | (v1 << 16), v2 | (v3 << 16));
            }
        }

        const uint32_t Ab = su + SM_A + buf*16384;
        const uint32_t Bb = su + SM_B + bstage*16384;
        #pragma unroll
        for (int ks = 0; ks < 4; ks++) {
            uint32_t af[4][4];
            #pragma unroll
            for (int am = 0; am < 4; am++) {
                uint32_t off = (uint32_t)((wm + am*16 + a_row)*128 + ks*32 + a_kb);
                ldmx4(af[am], Ab + sw128(off));
            }
            uint32_t bf[4][2];
            #pragma unroll
            for (int bp = 0; bp < 2; bp++) {
                uint32_t rr[4];
                uint32_t off = (uint32_t)((wn + bp*16 + b_row)*128 + ks*32 + b_kb);
                ldmx4(rr, Bb + sw128(off));
                bf[2*bp][0] = rr[0]; bf[2*bp][1] = rr[1];
                bf[2*bp+1][0] = rr[2]; bf[2*bp+1][1] = rr[3];
            }
            #pragma unroll
            for (int am = 0; am < 4; am++)
                #pragma unroll
                for (int bn = 0; bn < 4; bn++)
                    mma16816(acc[am][bn], af[am], bf[bn]);
        }

        if (more) {
            char* abase = smem + SM_A + (buf^1)*16384;
            #pragma unroll
            for (int q = 0; q < 8; q++)
                *(uint2*)(abase + stA[q]) = sA[q];
        }
        CP_WAIT2();
        __syncthreads();
    }

    // ---- epilogue ----
    const float* tp = d_t + b*COUT;
    #pragma unroll
    for (int am = 0; am < 4; am++) {
        int mr0 = tile*128 + wm + am*16 + (lane >> 2);
        #pragma unroll
        for (int half = 0; half < 2; half++) {
            int mp = mr0 + half*8;
            int h = mp / PADW;
            int w = mp - h*PADW;
            bool valid = (h < Hs) && (w < Ws);
            float* op = out + (size_t)b*(COUT*HW) + h*Ws + w;
            #pragma unroll
            for (int bn = 0; bn < 4; bn++) {
                int n = nh*128 + wn + bn*8 + 2*(lane & 3);
                float v0 = fmaf(acc[am][bn][half*2+0], inv_s[n],   add_s[n]);
                float v1 = fmaf(acc[am][bn][half*2+1], inv_s[n+1], add_s[n+1]);
                v0 = fmaxf(v0, 0.f) * __ldg(tp + n);
                v1 = fmaxf(v1, 0.f) * __ldg(tp + n + 1);
                if (valid) {
                    op[(size_t)n * HW] = v0;
                    op[(size_t)(n+1) * HW] = v1;
                }
            }
        }
    }
}

// ---------------------------------------------------------------------------
extern "C" void kernel_launch(void* const* d_in, const int* in_sizes, int n_in,
                              void* d_out, int out_size) {
    const float* x     = (const float*)d_in[0];
    const float* cw    = (const float*)d_in[1];
    const float* gw    = (const float*)d_in[2];
    const float* gb    = (const float*)d_in[3];
    const float* gamma = (const float*)d_in[4];
    const float* beta  = (const float*)d_in[5];
    const float* mean  = (const float*)d_in[6];
    const float* var   = (const float*)d_in[7];
    float* out = (float*)d_out;

    static bool attr_set = false;
    if (!attr_set) {
        cudaFuncSetAttribute(conv_mma_kernel,
                             cudaFuncAttributeMaxDynamicSharedMemorySize, SMEM_SZ);
        attr_set = true;
    }

    prep_x_kernel<<<B_*CIN, 256>>>(x);
    gate_kernel<<<B_, 256>>>(gw, gb);
    prep_w_kernel<<<NIMG, 256>>>(cw);
    dim3 grid(2, B_*TPB);
    conv_mma_kernel<<<grid, 256, SMEM_SZ>>>(gamma, beta, mean, var, out);
}

// round 9
// speedup vs baseline: 3.0057x; 1.0053x over previous
#include <cuda_runtime.h>
#include <cuda_fp16.h>
#include <cstdint>

#define B_    32
#define CIN   256
#define COUT  256
#define Hs    56
#define Ws    56
#define HW    3136
#define Kdim  2304
#define KZERO 128
#define NIMG  36           /* 64-k chunks */
#define BTILE 32768        /* bytes per 64-k B image (256 n) */
#define PADW  57
#define SLAB  3368
#define TPB   25           /* m'-tiles of 128 per batch */
#define NTILE (B_*TPB)     /* 800 tiles per n-half */

// ---------------- device scratch ----------------
__device__ float d_s[B_*CIN];
__device__ float d_t[B_*COUT];
__device__ __half d_xh[(size_t)B_*CIN*SLAB];
__device__ __align__(16) __half d_bimg[(size_t)NIMG*256*64];
__device__ unsigned int d_ctr[2];

// ---------------------------------------------------------------------------
// P0: padded fp16 slab (border-only zeroing) + abs-mean
// ---------------------------------------------------------------------------
__global__ void prep_x_kernel(const float* __restrict__ x) {
    int bc = blockIdx.x;
    int t = threadIdx.x;
    const float* xs = x + (size_t)bc * HW;
    size_t sb = (size_t)bc * SLAB;
    // border zeros only: row 0, rows 57-58, col 0 of rows 1-56, tail pad
    if (t < PADW)        d_xh[sb + t] = __float2half(0.f);
    if (t < 2*PADW)      d_xh[sb + 57*PADW + t] = __float2half(0.f);
    if (t < 56)          d_xh[sb + (t+1)*PADW] = __float2half(0.f);
    if (t < 5)           d_xh[sb + 3363 + t] = __float2half(0.f);
    float sum = 0.f;
    for (int j = t; j < HW; j += 256) {
        float v = xs[j];
        int hy = j / Ws, wx = j - hy*Ws;
        d_xh[sb + (hy+1)*PADW + wx + 1] = __float2half(v);
        sum += fabsf(v);
    }
    __shared__ float red[256];
    red[t] = sum;
    __syncthreads();
    for (int s = 128; s > 0; s >>= 1) {
        if (t < s) red[t] += red[t + s];
        __syncthreads();
    }
    if (t == 0) d_s[bc] = red[0] * (1.0f / HW);
}

// ---------------------------------------------------------------------------
// P1: pre-swizzled fp16 B images (row n: 128B = 64 fp16 along k, SW128)
// ---------------------------------------------------------------------------
__global__ void prep_w_kernel(const float* __restrict__ cw) {
    int c = blockIdx.x;
    int n = threadIdx.x;
    char* dst = (char*)d_bimg + (size_t)c * BTILE;
    const float* wr = cw + (size_t)n * Kdim + c*64;
    for (int kk = 0; kk < 64; kk++) {
        uint32_t off = (uint32_t)(n*128 + kk*2);
        off ^= (off >> 3) & 0x70;
        *(__half*)(dst + off) = __float2half(wr[kk]);
    }
}

// ---------------------------------------------------------------------------
// P2: gate (+ work counters reset; runs before conv, stream-ordered)
// ---------------------------------------------------------------------------
__global__ void gate_kernel(const float* __restrict__ gw,
                            const float* __restrict__ gb) {
    int b = blockIdx.x;
    int c = threadIdx.x;
    if (b == 0 && c < 2) d_ctr[c] = 0;
    __shared__ float s_sh[CIN];
    __shared__ float g_sh[COUT];
    __shared__ float red[256];

    s_sh[c] = d_s[b*CIN + c];
    __syncthreads();

    const float* wrow = gw + (size_t)c * CIN;
    float acc = gb[c];
    #pragma unroll 8
    for (int j = 0; j < CIN; j++) acc = fmaf(s_sh[j], wrow[j], acc);
    float g = fmaxf(acc, 0.f);
    g_sh[c] = g;
    __syncthreads();

    int rank = 0;
    for (int j = 0; j < COUT; j++) {
        float gj = g_sh[j];
        rank += (gj < g) || (gj == g && j < c);
    }
    float t = (rank < KZERO) ? 0.f : g;

    red[c] = t;
    __syncthreads();
    for (int s = 128; s > 0; s >>= 1) {
        if (c < s) red[c] += red[c + s];
        __syncthreads();
    }
    d_t[b*COUT + c] = t * ((float)COUT / red[0]);
}

// ---------------------------------------------------------------------------
// Main: persistent mma.sync fp16 implicit GEMM, 2 CTAs/SM, atomic tiling.
// CTA fixed n-half; pops 128-m' tiles. B = continuous 4-stage cp.async ring
// (chunk stream identical across tiles, 36 % 4 == 0). A = per-tile gather.
// ---------------------------------------------------------------------------
#define SM_A    0
#define SM_B    32768
#define SM_KOFF 98304
#define SM_INV  107520
#define SM_ADD  108544
#define SM_TILE 109568
#define SMEM_SZ 109600

__device__ __forceinline__ uint32_t smem_u32(const void* p) {
    uint32_t a;
    asm("{ .reg .u64 t; cvta.to.shared.u64 t, %1; cvt.u32.u64 %0, t; }" : "=r"(a) : "l"(p));
    return a;
}
__device__ __forceinline__ void ldmx4(uint32_t* r, uint32_t addr) {
    asm volatile("ldmatrix.sync.aligned.m8n8.x4.shared.b16 {%0,%1,%2,%3}, [%4];"
        : "=r"(r[0]), "=r"(r[1]), "=r"(r[2]), "=r"(r[3]) : "r"(addr));
}
__device__ __forceinline__ void mma16816(float* c, const uint32_t* a, const uint32_t* b) {
    asm volatile(
        "mma.sync.aligned.m16n8k16.row.col.f32.f16.f16.f32 "
        "{%0,%1,%2,%3}, {%4,%5,%6,%7}, {%8,%9}, {%0,%1,%2,%3};"
        : "+f"(c[0]), "+f"(c[1]), "+f"(c[2]), "+f"(c[3])
        : "r"(a[0]), "r"(a[1]), "r"(a[2]), "r"(a[3]), "r"(b[0]), "r"(b[1]));
}
__device__ __forceinline__ uint32_t sw128(uint32_t off) {
    return off ^ ((off >> 3) & 0x70);
}
__device__ __forceinline__ void cp16(uint32_t saddr, const void* g) {
    asm volatile("cp.async.cg.shared.global [%0], [%1], 16;" :: "r"(saddr), "l"(g) : "memory");
}
#define CP_COMMIT() asm volatile("cp.async.commit_group;" ::: "memory")
#define CP_WAIT2()  asm volatile("cp.async.wait_group 2;" ::: "memory")
#define CP_WAIT0()  asm volatile("cp.async.wait_group 0;" ::: "memory")

__global__ void __launch_bounds__(256, 2)
conv_mma_kernel(const float* __restrict__ gamma, const float* __restrict__ beta,
                const float* __restrict__ mean,  const float* __restrict__ var,
                float* __restrict__ out)
{
    extern __shared__ __align__(1024) char smem[];
    uint32_t* koff_s = (uint32_t*)(smem + SM_KOFF);
    float* inv_s = (float*)(smem + SM_INV);
    float* add_s = (float*)(smem + SM_ADD);
    volatile unsigned int* tile_s = (volatile unsigned int*)(smem + SM_TILE);
    const uint32_t su = smem_u32(smem);

    const int t = threadIdx.x;
    const int lane = t & 31;
    const int wrp = t >> 5;
    const int wm = (wrp & 1) * 64;
    const int wn = (wrp >> 1) * 32;
    const int nh = blockIdx.x & 1;

    for (int k = t; k < Kdim; k += 256) {
        int ci = k / 9, rs = k - ci*9;
        int dh = rs / 3, dw = rs - dh*3;
        koff_s[k] = (uint32_t)(ci*SLAB + dh*PADW + dw);
    }
    {
        float iv = gamma[t] * rsqrtf(var[t] + 1e-5f);
        inv_s[t] = iv;
        add_s[t] = beta[t] - mean[t]*iv;
    }
    __syncthreads();

    const int r = t & 127;
    const int kqb = (t >> 7) * 8;      // 0 or 8
    uint32_t stA[8];
    #pragma unroll
    for (int q = 0; q < 8; q++)
        stA[q] = sw128((uint32_t)(r*128 + (kqb + q)*8));

    const int a_row = (lane & 15);
    const int a_kb  = (lane & 16) ? 16 : 0;
    const int b_row = ((lane & 16) ? 8 : 0) + (lane & 7);
    const int b_kb  = (lane & 8) ? 16 : 0;

    const char* bsrc = (const char*)d_bimg + (size_t)nh * 16384;

    // ---- B ring prologue: chunks 0,1,2 into stages 0,1,2 ----
    #pragma unroll
    for (int pc = 0; pc < 3; pc++) {
        const char* src = bsrc + (size_t)pc * BTILE;
        uint32_t dst = su + SM_B + pc*16384;
        #pragma unroll
        for (int q = 0; q < 4; q++)
            cp16(dst + (uint32_t)(q*256 + t)*16, src + (q*256 + t)*16);
        CP_COMMIT();
    }

    for (;;) {
        if (t == 0) *tile_s = atomicAdd(&d_ctr[nh], 1u);
        __syncthreads();                     // also separates prior tile's smem reads
        const unsigned tile = *tile_s;
        if (tile >= NTILE) break;
        const int b    = tile / TPB;
        const int tloc = tile - b*TPB;
        const unsigned short* xbase = (const unsigned short*)d_xh
            + (size_t)b * (CIN*SLAB) + tloc*128 + r;

        // ---- A prologue: chunk 0 -> buf 0 ----
        {
            char* abase = smem + SM_A;
            #pragma unroll
            for (int q = 0; q < 8; q++) {
                uint4 e = *(const uint4*)(koff_s + (kqb + q)*4);
                uint32_t v0 = xbase[e.x];
                uint32_t v1 = xbase[e.y];
                uint32_t v2 = xbase[e.z];
                uint32_t v3 = xbase[e.w];
                *(uint2*)(abase + stA[q]) = make_uint2(v0 | (v1 << 16), v2 | (v3 << 16));
            }
        }
        CP_WAIT2();          // stage 0 of this pass guaranteed resident
        __syncthreads();

        float acc[4][4][4];
        #pragma unroll
        for (int i = 0; i < 4; i++)
            #pragma unroll
            for (int j = 0; j < 4; j++)
                #pragma unroll
                for (int q = 0; q < 4; q++) acc[i][j][q] = 0.f;

        for (int c = 0; c < NIMG; c++) {
            const int buf = c & 1;
            const bool more = (c + 1 < NIMG);

            // B prefetch (c+3) mod 36 — stream continues into next tile
            {
                int pc = c + 3; if (pc >= NIMG) pc -= NIMG;
                const char* src = bsrc + (size_t)pc * BTILE;
                uint32_t dst = su + SM_B + (pc & 3)*16384;
                #pragma unroll
                for (int q = 0; q < 4; q++)
                    cp16(dst + (uint32_t)(q*256 + t)*16, src + (q*256 + t)*16);
            }
            CP_COMMIT();

            uint2 sA[8];
            if (more) {
                const int k0 = (c + 1)*64;
                #pragma unroll
                for (int q = 0; q < 8; q++) {
                    uint4 e = *(const uint4*)(koff_s + k0 + (kqb + q)*4);
                    uint32_t v0 = xbase[e.x];
                    uint32_t v1 = xbase[e.y];
                    uint32_t v2 = xbase[e.z];
                    uint32_t v3 = xbase[e.w];
                    sA[q] = make_uint2(v0 | (v1 << 16), v2 | (v3 << 16));
                }
            }

            const uint32_t Ab = su + SM_A + buf*16384;
            const uint32_t Bb = su + SM_B + (c & 3)*16384;
            #pragma unroll
            for (int ks = 0; ks < 4; ks++) {
                uint32_t af[4][4];
                #pragma unroll
                for (int am = 0; am < 4; am++) {
                    uint32_t off = (uint32_t)((wm + am*16 + a_row)*128 + ks*32 + a_kb);
                    ldmx4(af[am], Ab + sw128(off));
                }
                uint32_t bf[4][2];
                #pragma unroll
                for (int bp = 0; bp < 2; bp++) {
                    uint32_t rr[4];
                    uint32_t off = (uint32_t)((wn + bp*16 + b_row)*128 + ks*32 + b_kb);
                    ldmx4(rr, Bb + sw128(off));
                    bf[2*bp][0] = rr[0]; bf[2*bp][1] = rr[1];
                    bf[2*bp+1][0] = rr[2]; bf[2*bp+1][1] = rr[3];
                }
                #pragma unroll
                for (int am = 0; am < 4; am++)
                    #pragma unroll
                    for (int bn = 0; bn < 4; bn++)
                        mma16816(acc[am][bn], af[am], bf[bn]);
            }

            if (more) {
                char* abase = smem + SM_A + (buf^1)*16384;
                #pragma unroll
                for (int q = 0; q < 8; q++)
                    *(uint2*)(abase + stA[q]) = sA[q];
            }
            CP_WAIT2();
            __syncthreads();
        }

        // ---- epilogue: BN + ReLU + gate, predicated NCHW store ----
        const float* tp = d_t + b*COUT;
        #pragma unroll
        for (int am = 0; am < 4; am++) {
            int mr0 = tloc*128 + wm + am*16 + (lane >> 2);
            #pragma unroll
            for (int half = 0; half < 2; half++) {
                int mp = mr0 + half*8;
                int h = mp / PADW;
                int w = mp - h*PADW;
                bool valid = (h < Hs) && (w < Ws);
                float* op = out + (size_t)b*(COUT*HW) + h*Ws + w;
                #pragma unroll
                for (int bn = 0; bn < 4; bn++) {
                    int n = nh*128 + wn + bn*8 + 2*(lane & 3);
                    float v0 = fmaf(acc[am][bn][half*2+0], inv_s[n],   add_s[n]);
                    float v1 = fmaf(acc[am][bn][half*2+1], inv_s[n+1], add_s[n+1]);
                    v0 = fmaxf(v0, 0.f) * __ldg(tp + n);
                    v1 = fmaxf(v1, 0.f) * __ldg(tp + n + 1);
                    if (valid) {
                        op[(size_t)n * HW] = v0;
                        op[(size_t)(n+1) * HW] = v1;
                    }
                }
            }
        }
    }
    CP_WAIT0();   // drain outstanding cp.async before exit
}

// ---------------------------------------------------------------------------
extern "C" void kernel_launch(void* const* d_in, const int* in_sizes, int n_in,
                              void* d_out, int out_size) {
    const float* x     = (const float*)d_in[0];
    const float* cw    = (const float*)d_in[1];
    const float* gw    = (const float*)d_in[2];
    const float* gb    = (const float*)d_in[3];
    const float* gamma = (const float*)d_in[4];
    const float* beta  = (const float*)d_in[5];
    const float* mean  = (const float*)d_in[6];
    const float* var   = (const float*)d_in[7];
    float* out = (float*)d_out;

    static bool attr_set = false;
    if (!attr_set) {
        cudaFuncSetAttribute(conv_mma_kernel,
                             cudaFuncAttributeMaxDynamicSharedMemorySize, SMEM_SZ);
        attr_set = true;
    }

    prep_x_kernel<<<B_*CIN, 256>>>(x);
    gate_kernel<<<B_, 256>>>(gw, gb);
    prep_w_kernel<<<NIMG, 256>>>(cw);
    conv_mma_kernel<<<296, 256, SMEM_SZ>>>(gamma, beta, mean, var, out);
}